// round 14
// baseline (speedup 1.0000x reference)
#include <cuda_runtime.h>
#include <cstdint>

// Problem constants
#define Bn      32
#define Tn      24
#define Sn      768
#define SPLIT   8                // CTAs per cluster (per batch)
#define KT      (Sn / SPLIT)     // 96 output columns per CTA
#define CT      3                // column tiles of 32 floats per CTA
#define STR     4                // row stripes
#define NW      (CT * STR)       // 12 warps
#define NTHR    (NW * 32)        // 384 threads
#define RSTRIDE (4 * STR)        // 16 rows between a thread's iterations
#define JG      8                // front-batched loads per group
#define NG      (Sn / (RSTRIDE * JG))  // 6 groups per step

__device__ __forceinline__ uint32_t smem_u32(const void* p) {
    return (uint32_t)__cvta_generic_to_shared(p);
}

__global__ void __cluster_dims__(SPLIT, 1, 1) __launch_bounds__(NTHR, 2)
scan_matvec_kernel(const float* __restrict__ inp,
                   const float* __restrict__ param,
                   float* __restrict__ out)
{
    __shared__ float  ybuf[2][Sn];       // double-buffered y for this batch
    __shared__ float4 red[STR][KT / 4];  // [4][24] stripe partials

    const int tid  = threadIdx.x;
    const int w    = tid >> 5;
    const int lane = tid & 31;
    const int c    = w % CT;        // column tile (32 floats)
    const int s    = w / CT;        // row stripe
    const int qr   = lane >> 3;     // row within 4-row pack
    const int g    = lane & 7;      // float4 group within 32-float tile
    const int b    = blockIdx.x / SPLIT;

    uint32_t rank;
    asm("mov.u32 %0, %%cluster_ctarank;" : "=r"(rank));
    const int k0 = (int)rank * KT;
    const int i0 = 4 * s + qr;

    // 8-lane groups each load one aligned 128B line of one row:
    // 4 rows per warp-LDG -> nL=4; skip predicate is quarter-warp uniform.
    const float* Mth = inp + (size_t)b * Tn * Sn * Sn
                           + (size_t)i0 * Sn + (k0 + c * 32 + g * 4);

    // y0 = param + 1 (dense; no zeros expected at t=0)
    for (int i = tid; i < Sn; i += NTHR)
        ybuf[0][i] = param[i] + 1.0f;

    // cluster handshake before any DSMEM traffic later
    asm volatile("barrier.cluster.arrive.aligned;" ::: "memory");
    asm volatile("barrier.cluster.wait.aligned;"   ::: "memory");

    int p = 0;
    for (int t = 0; t < Tn; ++t) {
        const float* Mt = Mth + (size_t)t * Sn * Sn;
        const float* yp = ybuf[p];

        float ax = 0.f, ay = 0.f, az = 0.f, aw = 0.f;

        #pragma unroll
        for (int q = 0; q < NG; ++q) {
            float4 m[JG];
            float  yv[JG];
            // front-batched: up to 8 independent predicated LDG.128 in flight.
            // Zero-y rows issue nothing (no L1tex wavefront, no DRAM sectors).
            #pragma unroll
            for (int u = 0; u < JG; ++u) {
                const int j = q * JG + u;
                yv[u] = yp[i0 + j * RSTRIDE];
                float4 mv = make_float4(0.f, 0.f, 0.f, 0.f);
                if (yv[u] != 0.0f)
                    mv = __ldcs(reinterpret_cast<const float4*>(
                             Mt + (size_t)j * RSTRIDE * Sn));
                m[u] = mv;
            }
            #pragma unroll
            for (int u = 0; u < JG; ++u) {
                ax = fmaf(yv[u], m[u].x, ax);
                ay = fmaf(yv[u], m[u].y, ay);
                az = fmaf(yv[u], m[u].z, az);
                aw = fmaf(yv[u], m[u].w, aw);
            }
        }

        // combine the four row-quarters (same columns) within the warp:
        // down16: q0+=q2, q1+=q3 ; down8: q0+=q1  -> lanes 0-7 hold the sum
        ax += __shfl_down_sync(0xffffffffu, ax, 16);
        ay += __shfl_down_sync(0xffffffffu, ay, 16);
        az += __shfl_down_sync(0xffffffffu, az, 16);
        aw += __shfl_down_sync(0xffffffffu, aw, 16);
        ax += __shfl_down_sync(0xffffffffu, ax, 8);
        ay += __shfl_down_sync(0xffffffffu, ay, 8);
        az += __shfl_down_sync(0xffffffffu, az, 8);
        aw += __shfl_down_sync(0xffffffffu, aw, 8);

        if (qr == 0)
            red[s][c * 8 + g] = make_float4(ax, ay, az, aw);
        __syncthreads();

        // 24 threads: reduce 4 stripes, then relu + cluster broadcast
        if (tid < KT / 4) {
            float4 r = red[0][tid];
            #pragma unroll
            for (int ss = 1; ss < STR; ++ss) {
                float4 q4 = red[ss][tid];
                r.x += q4.x; r.y += q4.y; r.z += q4.z; r.w += q4.w;
            }
            if (t == Tn - 1) {
                // final step: PRE-ReLU y
                *reinterpret_cast<float4*>(out + (size_t)b * Sn + k0 + tid * 4) = r;
            } else {
                r.x = fmaxf(r.x, 0.f); r.y = fmaxf(r.y, 0.f);
                r.z = fmaxf(r.z, 0.f); r.w = fmaxf(r.w, 0.f);
                uint32_t la = smem_u32(&ybuf[p ^ 1][k0 + tid * 4]);
                #pragma unroll
                for (int rr = 0; rr < SPLIT; ++rr) {
                    uint32_t ra;
                    asm("mapa.shared::cluster.u32 %0, %1, %2;"
                        : "=r"(ra) : "r"(la), "r"(rr));
                    asm volatile("st.shared::cluster.v4.f32 [%0], {%1,%2,%3,%4};"
                                 :: "r"(ra), "f"(r.x), "f"(r.y), "f"(r.z), "f"(r.w)
                                 : "memory");
                }
            }
        }

        if (t < Tn - 1) {
            // one cluster barrier per step: release DSMEM y stores,
            // acquire before anyone reads ybuf[p^1]
            asm volatile("barrier.cluster.arrive.aligned;" ::: "memory");
            asm volatile("barrier.cluster.wait.aligned;"   ::: "memory");
            p ^= 1;
        }
    }
}

extern "C" void kernel_launch(void* const* d_in, const int* in_sizes, int n_in,
                              void* d_out, int out_size)
{
    const float* inp   = (const float*)d_in[0];   // [32, 24, 768, 768] f32
    const float* param = (const float*)d_in[1];   // [768] f32
    float* out = (float*)d_out;                   // [32, 768] f32

    (void)in_sizes; (void)n_in; (void)out_size;

    scan_matvec_kernel<<<Bn * SPLIT, NTHR>>>(inp, param, out);
}